// round 2
// baseline (speedup 1.0000x reference)
#include <cuda_runtime.h>
#include <cuda_bf16.h>
#include <cstdint>

#define BATCH   4096
#define INF     8192
#define OUTF    8192
#define NGRP    1024
#define WLEN    (NGRP * INF)

#define NCHUNK  64
#define RPC     (BATCH / NCHUNK)   // 64 rows per chunk

// Scratch (allocation-free rule: __device__ globals)
__device__ float g_partial[NCHUNK * INF];   // 2 MB
__device__ float g_s;

// ---------------------------------------------------------------------------
// K1: partial column sums. grid = (16, NCHUNK), block = 128 threads.
// Each thread owns one float4 column group (4 columns) within one row-chunk.
// ---------------------------------------------------------------------------
__global__ void __launch_bounds__(128) colsum_kernel(const float* __restrict__ x) {
    const int chunk = blockIdx.y;
    const int c4 = blockIdx.x * blockDim.x + threadIdx.x;      // 0..2047
    const size_t row_stride4 = INF / 4;                        // 2048
    const float4* __restrict__ xp =
        reinterpret_cast<const float4*>(x) + (size_t)chunk * RPC * row_stride4 + c4;

    float4 a0 = {0.f,0.f,0.f,0.f};
    float4 a1 = {0.f,0.f,0.f,0.f};
    float4 a2 = {0.f,0.f,0.f,0.f};
    float4 a3 = {0.f,0.f,0.f,0.f};

    #pragma unroll 4
    for (int r = 0; r < RPC; r += 4) {
        float4 v0 = xp[(size_t)(r + 0) * row_stride4];
        float4 v1 = xp[(size_t)(r + 1) * row_stride4];
        float4 v2 = xp[(size_t)(r + 2) * row_stride4];
        float4 v3 = xp[(size_t)(r + 3) * row_stride4];
        a0.x += v0.x; a0.y += v0.y; a0.z += v0.z; a0.w += v0.w;
        a1.x += v1.x; a1.y += v1.y; a1.z += v1.z; a1.w += v1.w;
        a2.x += v2.x; a2.y += v2.y; a2.z += v2.z; a2.w += v2.w;
        a3.x += v3.x; a3.y += v3.y; a3.z += v3.z; a3.w += v3.w;
    }
    float4 out;
    out.x = (a0.x + a1.x) + (a2.x + a3.x);
    out.y = (a0.y + a1.y) + (a2.y + a3.y);
    out.z = (a0.z + a1.z) + (a2.z + a3.z);
    out.w = (a0.w + a1.w) + (a2.w + a3.w);
    reinterpret_cast<float4*>(g_partial)[(size_t)chunk * row_stride4 + c4] = out;
}

// ---------------------------------------------------------------------------
// K2: single block (1024 threads). Finish the reduction, do the group logic,
// produce scalar s.
// ---------------------------------------------------------------------------
__global__ void __launch_bounds__(1024) scalar_kernel(
    const float* __restrict__ wflat,
    const float* __restrict__ mins,
    const float* __restrict__ maxs,
    const int*   __restrict__ start_pos,
    const int*   __restrict__ offsets,
    const int*   __restrict__ sizes)
{
    __shared__ float smins[NGRP];
    __shared__ float red[1024];
    const int t = threadIdx.x;
    smins[t] = mins[t];              // NGRP == blockDim == 1024
    __syncthreads();

    float acc = 0.f;
    #pragma unroll
    for (int c = 0; c < INF / 1024; c++) {
        const int j = c * 1024 + t;
        float sum = 0.f;
        #pragma unroll 8
        for (int k = 0; k < NCHUNK; k++)
            sum += g_partial[(size_t)k * INF + j];
        const float val = sum * (1.0f / (float)BATCH);

        // searchsorted(mins, val, side='right') - 1
        int lo = 0, hi = NGRP;
        while (lo < hi) {
            int mid = (lo + hi) >> 1;
            if (smins[mid] <= val) lo = mid + 1; else hi = mid;
        }
        const int g  = lo - 1;
        const int gc = min(max(g, 0), NGRP - 1);
        const bool hit = (g >= 0) && (val >= smins[gc]) && (val <= maxs[gc]);
        const int pos = j - start_pos[gc];
        const bool pos_ok = (pos >= 0) && (pos < sizes[gc]);

        float w = 0.f;
        if (hit && pos_ok) {
            long long idx = (long long)offsets[gc] + (long long)pos;
            idx = idx < 0 ? 0 : idx;
            idx = idx > (long long)(WLEN - 1) ? (long long)(WLEN - 1) : idx;
            w = wflat[idx];
        }
        acc += val * w;
    }

    red[t] = acc;
    __syncthreads();
    #pragma unroll
    for (int sft = 512; sft > 0; sft >>= 1) {
        if (t < sft) red[t] += red[t + sft];
        __syncthreads();
    }
    if (t == 0) g_s = red[0];
}

// ---------------------------------------------------------------------------
// K3: write the full 128 MB output. Row 0 gets mask ? s : 0, rest zeros.
// out_mask is a JAX bool array delivered as int32 (harness supports
// float32/int32/bf16 only) -> read as const int*.
// ---------------------------------------------------------------------------
__global__ void __launch_bounds__(256) writeout_kernel(
    float* __restrict__ out, const int* __restrict__ mask)
{
    const size_t total4 = (size_t)BATCH * OUTF / 4;
    const size_t stride = (size_t)gridDim.x * blockDim.x;
    size_t i4 = (size_t)blockIdx.x * blockDim.x + threadIdx.x;
    const float s = g_s;
    float4* __restrict__ o4 = reinterpret_cast<float4*>(out);

    for (; i4 < total4; i4 += stride) {
        float4 v = {0.f, 0.f, 0.f, 0.f};
        if (i4 < (size_t)(OUTF / 4)) {
            const int j = (int)i4 * 4;
            v.x = (mask[j + 0] != 0) ? s : 0.f;
            v.y = (mask[j + 1] != 0) ? s : 0.f;
            v.z = (mask[j + 2] != 0) ? s : 0.f;
            v.w = (mask[j + 3] != 0) ? s : 0.f;
        }
        o4[i4] = v;
    }
}

// ---------------------------------------------------------------------------
extern "C" void kernel_launch(void* const* d_in, const int* in_sizes, int n_in,
                              void* d_out, int out_size)
{
    const float* x         = (const float*)d_in[0];
    const float* wflat     = (const float*)d_in[1];
    const float* mins      = (const float*)d_in[2];
    const float* maxs      = (const float*)d_in[3];
    const int*   start_pos = (const int*)d_in[4];
    const int*   offsets   = (const int*)d_in[5];
    const int*   sizes     = (const int*)d_in[6];
    const int*   out_mask  = (const int*)d_in[7];
    float*       out       = (float*)d_out;

    // K1: (16 col-blocks of 512 cols) x (64 row-chunks of 64 rows)
    dim3 g1(16, NCHUNK);
    colsum_kernel<<<g1, 128>>>(x);

    // K2: scalar
    scalar_kernel<<<1, 1024>>>(wflat, mins, maxs, start_pos, offsets, sizes);

    // K3: 128 MB output write
    writeout_kernel<<<2048, 256>>>(out, out_mask);
}